// round 15
// baseline (speedup 1.0000x reference)
#include <cuda_runtime.h>
#include <cstddef>
#include <cstdint>

#define KP1 6
#define KSEL 5
#define NUM_USERS 20000
#define EMBED_DIM 64
#define ALPHA_F 0.7f
#define NTHREADS 256
#define NWARPS (NTHREADS / 32)
#define CAP 1024

#define NCHUNK 8
#define CHUNK_FLOATS 2500          // 10000 bytes, 16B-aligned
#define CHUNK_BYTES  (CHUNK_FLOATS * 4)
#define CHUNK_GROUPS (CHUNK_FLOATS / 4)   // 625 float4 groups
#define ROW_BYTES    (NUM_USERS * 4)      // 80000
// dynamic smem: row buffer + 8 mbarriers + candidate arrays
#define SMEM_DYN     (ROW_BYTES + 64 + CAP * 8)

struct __align__(8) VI { float v; int i; };

__device__ __forceinline__ bool better(float av, int ai, float bv, int bi) {
    // jax.lax.top_k order: descending value, ties -> lower index first.
    return (av > bv) || (av == bv && ai < bi);
}

__device__ __forceinline__ void exact_insert(VI best[KP1], float v, int idx) {
    if (better(v, idx, best[KP1 - 1].v, best[KP1 - 1].i)) {
        best[KP1 - 1].v = v;
        best[KP1 - 1].i = idx;
        #pragma unroll
        for (int j = KP1 - 1; j > 0; j--) {
            if (better(best[j].v, best[j].i, best[j - 1].v, best[j - 1].i)) {
                VI tmp = best[j]; best[j] = best[j - 1]; best[j - 1] = tmp;
            }
        }
    }
}

__device__ __forceinline__ float fmax4(float4 f) {
    return fmaxf(fmaxf(f.x, f.y), fmaxf(f.z, f.w));
}

__device__ __forceinline__ void emit4(float4 f, int base, float T,
                                      int* s_count, float* s_cval, int* s_cidx) {
    if (f.x >= T) { int p = atomicAdd(s_count, 1); if (p < CAP) { s_cval[p] = f.x; s_cidx[p] = base + 0; } }
    if (f.y >= T) { int p = atomicAdd(s_count, 1); if (p < CAP) { s_cval[p] = f.y; s_cidx[p] = base + 1; } }
    if (f.z >= T) { int p = atomicAdd(s_count, 1); if (p < CAP) { s_cval[p] = f.z; s_cidx[p] = base + 2; } }
    if (f.w >= T) { int p = atomicAdd(s_count, 1); if (p < CAP) { s_cval[p] = f.w; s_cidx[p] = base + 3; } }
}

// ---- async-copy primitives ----
__device__ __forceinline__ uint32_t smem_u32(const void* p) {
    return (uint32_t)__cvta_generic_to_shared(p);
}
__device__ __forceinline__ void mbar_init(uint32_t mbar, uint32_t count) {
    asm volatile("mbarrier.init.shared.b64 [%0], %1;" :: "r"(mbar), "r"(count) : "memory");
}
__device__ __forceinline__ void mbar_expect_tx(uint32_t mbar, uint32_t bytes) {
    asm volatile("mbarrier.arrive.expect_tx.shared.b64 _, [%0], %1;"
                 :: "r"(mbar), "r"(bytes) : "memory");
}
__device__ __forceinline__ void bulk_g2s(uint32_t dst, const void* src,
                                         uint32_t bytes, uint32_t mbar) {
    asm volatile(
        "cp.async.bulk.shared::cluster.global.mbarrier::complete_tx::bytes "
        "[%0], [%1], %2, [%3];"
        :: "r"(dst), "l"(src), "r"(bytes), "r"(mbar) : "memory");
}
__device__ __forceinline__ void mbar_wait(uint32_t mbar, uint32_t parity) {
    asm volatile(
        "{\n\t.reg .pred P;\n\t"
        "WAIT_%=:\n\t"
        "mbarrier.try_wait.parity.acquire.cta.shared::cta.b64 P, [%0], %1, 0x989680;\n\t"
        "@P bra.uni DONE_%=;\n\t"
        "bra.uni WAIT_%=;\n\t"
        "DONE_%=:\n\t}"
        :: "r"(mbar), "r"(parity) : "memory");
}
__device__ __forceinline__ void fence_async() {
    asm volatile("fence.proxy.async.shared::cta;" ::: "memory");
}

__global__ __launch_bounds__(NTHREADS)
void user_blend_kernel(const int* __restrict__ user_idx,
                       const float* __restrict__ emb,
                       const float* __restrict__ cooc,
                       float* __restrict__ out)
{
    extern __shared__ __align__(128) char dsm[];
    float* s_row  = reinterpret_cast<float*>(dsm);                       // 80000 B
    unsigned long long* s_mb = reinterpret_cast<unsigned long long*>(dsm + ROW_BYTES); // 64 B
    float* s_cval = reinterpret_cast<float*>(dsm + ROW_BYTES + 64);      // 4096 B
    int*   s_cidx = reinterpret_cast<int*>(dsm + ROW_BYTES + 64 + CAP * 4); // 4096 B

    __shared__ float s_wmax[NWARPS];
    __shared__ int   s_count;
    __shared__ float s_w[KSEL];
    __shared__ int   s_idx[KSEL];

    const int t = threadIdx.x;
    const int lane = t & 31;
    const int warp = t >> 5;
    const int u = user_idx[blockIdx.x];
    const float* __restrict__ row = cooc + (size_t)u * NUM_USERS;

    if (t == 0) {
        s_count = 0;
        #pragma unroll
        for (int c = 0; c < NCHUNK; c++)
            mbar_init(smem_u32(&s_mb[c]), 1);
        fence_async();
    }
    __syncthreads();

    // Producer: issue ALL 8 chunk copies up-front. Each chunk has its own
    // buffer region and single-use mbarrier -> no reuse, no backpressure,
    // the full 80 KB row is in flight immediately.
    if (t == 0) {
        #pragma unroll
        for (int c = 0; c < NCHUNK; c++) {
            uint32_t mb = smem_u32(&s_mb[c]);
            mbar_expect_tx(mb, CHUNK_BYTES);
            bulk_g2s(smem_u32(&s_row[c * CHUNK_FLOATS]),
                     row + c * CHUNK_FLOATS, CHUNK_BYTES, mb);
        }
    }

    // ---------- Chunk 0: compute threshold T, then filter in place ----------
    mbar_wait(smem_u32(&s_mb[0]), 0);

    const float4* bp0 = reinterpret_cast<const float4*>(s_row);
    float pm = -3.0e38f;
    #pragma unroll
    for (int r = 0; r < 3; r++) {
        int g = t + r * NTHREADS;
        if (g < CHUNK_GROUPS) pm = fmaxf(pm, fmax4(bp0[g]));
    }
    {
        float wm = pm;
        #pragma unroll
        for (int s = 16; s >= 1; s >>= 1)
            wm = fmaxf(wm, __shfl_xor_sync(0xffffffffu, wm, s));
        if (lane == 0) s_wmax[warp] = wm;
    }
    __syncthreads();

    // Every thread redundantly computes T = 6th-largest of the 8 warp maxes.
    // Safe lower bound: the 6 largest warp-maxes are >=6 distinct row elements,
    // so T <= true 6th-largest of the row. Filter with >= preserves exactness.
    float T;
    {
        float top[KP1];
        #pragma unroll
        for (int j = 0; j < KP1; j++) top[j] = -3.0e38f;
        #pragma unroll
        for (int k = 0; k < NWARPS; k++) {
            float v = s_wmax[k];   // broadcast read
            #pragma unroll
            for (int j = 0; j < KP1; j++) {
                float lo = fminf(top[j], v);
                top[j]   = fmaxf(top[j], v);
                v = lo;
            }
        }
        T = top[KP1 - 1];
    }

    // Filter chunk 0 (smem-resident). Only threads whose max passed T rescan.
    if (pm >= T) {
        #pragma unroll
        for (int r = 0; r < 3; r++) {
            int g = t + r * NTHREADS;
            if (g < CHUNK_GROUPS) {
                float4 f = bp0[g];
                if (fmax4(f) >= T)
                    emit4(f, g * 4, T, &s_count, s_cval, s_cidx);
            }
        }
    }

    // ---------- Chunks 1..7: wait -> filter, no inter-chunk barriers ----------
    for (int c = 1; c < NCHUNK; c++) {
        mbar_wait(smem_u32(&s_mb[c]), 0);
        const float4* bp = reinterpret_cast<const float4*>(&s_row[c * CHUNK_FLOATS]);
        const int cbase = c * CHUNK_FLOATS;
        #pragma unroll
        for (int r = 0; r < 3; r++) {
            int g = t + r * NTHREADS;
            if (g < CHUNK_GROUPS) {
                float4 f = bp[g];
                if (fmax4(f) >= T)
                    emit4(f, cbase + g * 4, T, &s_count, s_cval, s_cidx);
            }
        }
    }
    __syncthreads();

    // ---------- Final exact top-6, softmax, weights (serial tail: proven) ----------
    if (t == 0) {
        VI best[KP1];
        #pragma unroll
        for (int j = 0; j < KP1; j++) { best[j].v = -3.0e38f; best[j].i = 0x7fffffff; }

        int cnt = s_count;
        if (cnt <= CAP) {
            for (int k = 0; k < cnt; k++)
                exact_insert(best, s_cval[k], s_cidx[k]);
        } else {
            // Overflow fallback (adversarial ties only): serial scan of the
            // smem-resident row (all chunks have landed by now).
            for (int k = 0; k < NUM_USERS; k++)
                exact_insert(best, s_row[k], k);
        }

        // Drop slot 0 (the max), softmax over slots 1..5.
        float m = best[1].v;
        float e[KSEL];
        float sum = 0.0f;
        #pragma unroll
        for (int j = 0; j < KSEL; j++) {
            e[j] = __expf(best[j + 1].v - m);
            sum += e[j];
        }
        float inv = 1.0f / sum;
        #pragma unroll
        for (int j = 0; j < KSEL; j++) {
            s_w[j]   = e[j] * inv;
            s_idx[j] = best[j + 1].i;
        }
    }
    __syncthreads();

    // ---------- Blend ----------
    if (t < EMBED_DIM) {
        float acc = 0.0f;
        #pragma unroll
        for (int j = 0; j < KSEL; j++)
            acc += s_w[j] * emb[(size_t)s_idx[j] * EMBED_DIM + t];
        float self = emb[(size_t)u * EMBED_DIM + t];
        out[(size_t)blockIdx.x * EMBED_DIM + t] = ALPHA_F * self + (1.0f - ALPHA_F) * acc;
    }
}

extern "C" void kernel_launch(void* const* d_in, const int* in_sizes, int n_in,
                              void* d_out, int out_size)
{
    // Identify inputs by element count:
    //   user_idx: 4096 (int32), emb: 20000*64 (f32), cooc: 20000*20000 (f32)
    const int*   user_idx = nullptr;
    const float* emb      = nullptr;
    const float* cooc     = nullptr;
    int batch = 0;
    for (int i = 0; i < n_in; i++) {
        long long sz = in_sizes[i];
        if (sz == (long long)NUM_USERS * NUM_USERS) {
            cooc = (const float*)d_in[i];
        } else if (sz == (long long)NUM_USERS * EMBED_DIM) {
            emb = (const float*)d_in[i];
        } else {
            user_idx = (const int*)d_in[i];
            batch = (int)sz;
        }
    }
    float* out = (float*)d_out;
    // Opt in to >48 KB dynamic shared memory (attribute set, not an allocation).
    cudaFuncSetAttribute(user_blend_kernel,
                         cudaFuncAttributeMaxDynamicSharedMemorySize, SMEM_DYN);
    user_blend_kernel<<<batch, NTHREADS, SMEM_DYN>>>(user_idx, emb, cooc, out);
}

// round 16
// speedup vs baseline: 2.2438x; 2.2438x over previous
#include <cuda_runtime.h>
#include <cstddef>

#define KP1 6
#define KSEL 5
#define NUM_USERS 20000
#define ROW4 (NUM_USERS / 4)       // 5000 float4 groups
#define EMBED_DIM 64
#define ALPHA_F 0.7f
#define NTHREADS 256
#define NWARPS (NTHREADS / 32)
#define CAP 1024

struct __align__(8) VI { float v; int i; };

__device__ __forceinline__ bool better(float av, int ai, float bv, int bi) {
    // jax.lax.top_k order: descending value, ties -> lower index first.
    return (av > bv) || (av == bv && ai < bi);
}

__device__ __forceinline__ void exact_insert(VI best[KP1], float v, int idx) {
    if (better(v, idx, best[KP1 - 1].v, best[KP1 - 1].i)) {
        best[KP1 - 1].v = v;
        best[KP1 - 1].i = idx;
        #pragma unroll
        for (int j = KP1 - 1; j > 0; j--) {
            if (better(best[j].v, best[j].i, best[j - 1].v, best[j - 1].i)) {
                VI tmp = best[j]; best[j] = best[j - 1]; best[j - 1] = tmp;
            }
        }
    }
}

__device__ __forceinline__ float fmax4(float4 f) {
    return fmaxf(fmaxf(f.x, f.y), fmaxf(f.z, f.w));
}

__device__ __forceinline__ void emit4(float4 f, int base, float T,
                                      int* s_count, float* s_cval, int* s_cidx) {
    if (f.x >= T) { int p = atomicAdd(s_count, 1); if (p < CAP) { s_cval[p] = f.x; s_cidx[p] = base + 0; } }
    if (f.y >= T) { int p = atomicAdd(s_count, 1); if (p < CAP) { s_cval[p] = f.y; s_cidx[p] = base + 1; } }
    if (f.z >= T) { int p = atomicAdd(s_count, 1); if (p < CAP) { s_cval[p] = f.z; s_cidx[p] = base + 2; } }
    if (f.w >= T) { int p = atomicAdd(s_count, 1); if (p < CAP) { s_cval[p] = f.w; s_cidx[p] = base + 3; } }
}

__global__ __launch_bounds__(NTHREADS, 7)
void user_blend_kernel(const int* __restrict__ user_idx,
                       const float* __restrict__ emb,
                       const float* __restrict__ cooc,
                       float* __restrict__ out)
{
    __shared__ float s_wmax[NWARPS];
    __shared__ float s_cval[CAP];
    __shared__ int   s_cidx[CAP];
    __shared__ int   s_count;
    __shared__ float s_w[KSEL];
    __shared__ int   s_idx[KSEL];

    const int t = threadIdx.x;
    const int lane = t & 31;
    const int warp = t >> 5;
    const int u = user_idx[blockIdx.x];
    const float4* __restrict__ row4 =
        reinterpret_cast<const float4*>(cooc + (size_t)u * NUM_USERS);

    // ---------- Phase 0: threshold from the first 4096 elements ----------
    {
        float4 a = row4[t];
        float4 b = row4[t + NTHREADS];
        float4 c = row4[t + 2 * NTHREADS];
        float4 d = row4[t + 3 * NTHREADS];
        float pm = fmaxf(fmaxf(fmax4(a), fmax4(b)), fmaxf(fmax4(c), fmax4(d)));
        #pragma unroll
        for (int s = 16; s >= 1; s >>= 1)
            pm = fmaxf(pm, __shfl_xor_sync(0xffffffffu, pm, s));
        if (lane == 0) s_wmax[warp] = pm;
        if (t == 0) s_count = 0;
    }
    __syncthreads();

    // Every thread redundantly computes T = 6th-largest of the 8 warp maxes.
    // Safe lower bound: the 6 largest warp-maxes are >=6 distinct row elements,
    // so T <= true 6th-largest of the row. Filter with >= preserves exactness.
    float T;
    {
        float top[KP1];
        #pragma unroll
        for (int j = 0; j < KP1; j++) top[j] = -3.0e38f;
        #pragma unroll
        for (int k = 0; k < NWARPS; k++) {
            float v = s_wmax[k];   // broadcast read
            #pragma unroll
            for (int j = 0; j < KP1; j++) {
                float lo = fminf(top[j], v);
                top[j]   = fmaxf(top[j], v);
                v = lo;
            }
        }
        T = top[KP1 - 1];
    }

    // ---------- Phase 1a: groups 0..4095, unclamped 4-deep batches ----------
    #pragma unroll 1
    for (int b = 0; b < 4; b++) {
        int i0 = t + b * 4 * NTHREADS;
        float4 a = row4[i0];
        float4 c = row4[i0 + NTHREADS];
        float4 d = row4[i0 + 2 * NTHREADS];
        float4 e = row4[i0 + 3 * NTHREADS];
        float ma = fmax4(a);
        float mc = fmax4(c);
        float md = fmax4(d);
        float me = fmax4(e);
        float bm = fmaxf(fmaxf(ma, mc), fmaxf(md, me));
        if (bm >= T) {                 // rare
            if (ma >= T) emit4(a, i0 * 4,                  T, &s_count, s_cval, s_cidx);
            if (mc >= T) emit4(c, (i0 + NTHREADS) * 4,     T, &s_count, s_cval, s_cidx);
            if (md >= T) emit4(d, (i0 + 2 * NTHREADS) * 4, T, &s_count, s_cval, s_cidx);
            if (me >= T) emit4(e, (i0 + 3 * NTHREADS) * 4, T, &s_count, s_cval, s_cidx);
        }
    }

    // ---------- Phase 1b: tail groups 4096..4999 (the only clamped batch) ----------
    {
        int i0 = t + 4 * 4 * NTHREADS;          // 4096 + t
        int i1 = i0 + NTHREADS;
        int i2 = i0 + 2 * NTHREADS;
        int i3 = i0 + 3 * NTHREADS;
        float4 a = row4[min(i0, ROW4 - 1)];
        float4 c = row4[min(i1, ROW4 - 1)];
        float4 d = row4[min(i2, ROW4 - 1)];
        float4 e = row4[min(i3, ROW4 - 1)];
        float ma = (i0 < ROW4) ? fmax4(a) : -3.0e38f;
        float mc = (i1 < ROW4) ? fmax4(c) : -3.0e38f;
        float md = (i2 < ROW4) ? fmax4(d) : -3.0e38f;
        float me = (i3 < ROW4) ? fmax4(e) : -3.0e38f;
        float bm = fmaxf(fmaxf(ma, mc), fmaxf(md, me));
        if (bm >= T) {
            if (ma >= T) emit4(a, i0 * 4, T, &s_count, s_cval, s_cidx);
            if (mc >= T) emit4(c, i1 * 4, T, &s_count, s_cval, s_cidx);
            if (md >= T) emit4(d, i2 * 4, T, &s_count, s_cval, s_cidx);
            if (me >= T) emit4(e, i3 * 4, T, &s_count, s_cval, s_cidx);
        }
    }
    __syncthreads();

    // ---------- Final exact top-6, softmax, weights ----------
    if (t == 0) {
        VI best[KP1];
        #pragma unroll
        for (int j = 0; j < KP1; j++) { best[j].v = -3.0e38f; best[j].i = 0x7fffffff; }

        int cnt = s_count;
        if (cnt <= CAP) {
            for (int k = 0; k < cnt; k++)
                exact_insert(best, s_cval[k], s_cidx[k]);
        } else {
            // Overflow fallback (adversarial ties only): serial exact scan.
            const float* row = cooc + (size_t)u * NUM_USERS;
            for (int k = 0; k < NUM_USERS; k++)
                exact_insert(best, row[k], k);
        }

        // Drop slot 0 (the max), softmax over slots 1..5.
        float m = best[1].v;
        float e[KSEL];
        float sum = 0.0f;
        #pragma unroll
        for (int j = 0; j < KSEL; j++) {
            e[j] = __expf(best[j + 1].v - m);
            sum += e[j];
        }
        float inv = 1.0f / sum;
        #pragma unroll
        for (int j = 0; j < KSEL; j++) {
            s_w[j]   = e[j] * inv;
            s_idx[j] = best[j + 1].i;
        }
    }
    __syncthreads();

    // ---------- Blend ----------
    if (t < EMBED_DIM) {
        float acc = 0.0f;
        #pragma unroll
        for (int j = 0; j < KSEL; j++)
            acc += s_w[j] * emb[(size_t)s_idx[j] * EMBED_DIM + t];
        float self = emb[(size_t)u * EMBED_DIM + t];
        out[(size_t)blockIdx.x * EMBED_DIM + t] = ALPHA_F * self + (1.0f - ALPHA_F) * acc;
    }
}

extern "C" void kernel_launch(void* const* d_in, const int* in_sizes, int n_in,
                              void* d_out, int out_size)
{
    // Identify inputs by element count:
    //   user_idx: 4096 (int32), emb: 20000*64 (f32), cooc: 20000*20000 (f32)
    const int*   user_idx = nullptr;
    const float* emb      = nullptr;
    const float* cooc     = nullptr;
    int batch = 0;
    for (int i = 0; i < n_in; i++) {
        long long sz = in_sizes[i];
        if (sz == (long long)NUM_USERS * NUM_USERS) {
            cooc = (const float*)d_in[i];
        } else if (sz == (long long)NUM_USERS * EMBED_DIM) {
            emb = (const float*)d_in[i];
        } else {
            user_idx = (const int*)d_in[i];
            batch = (int)sz;
        }
    }
    float* out = (float*)d_out;
    user_blend_kernel<<<batch, NTHREADS>>>(user_idx, emb, cooc, out);
}

// round 17
// speedup vs baseline: 2.3623x; 1.0528x over previous
#include <cuda_runtime.h>
#include <cstddef>

#define KP1 6
#define KSEL 5
#define NUM_USERS 20000
#define ROW4 (NUM_USERS / 4)       // 5000 float4 groups
#define EMBED_DIM 64
#define ALPHA_F 0.7f
#define NTHREADS 256
#define NWARPS (NTHREADS / 32)
#define CAP 1024

struct __align__(8) VI { float v; int i; };

__device__ __forceinline__ bool better(float av, int ai, float bv, int bi) {
    // jax.lax.top_k order: descending value, ties -> lower index first.
    return (av > bv) || (av == bv && ai < bi);
}

__device__ __forceinline__ void exact_insert(VI best[KP1], float v, int idx) {
    if (better(v, idx, best[KP1 - 1].v, best[KP1 - 1].i)) {
        best[KP1 - 1].v = v;
        best[KP1 - 1].i = idx;
        #pragma unroll
        for (int j = KP1 - 1; j > 0; j--) {
            if (better(best[j].v, best[j].i, best[j - 1].v, best[j - 1].i)) {
                VI tmp = best[j]; best[j] = best[j - 1]; best[j - 1] = tmp;
            }
        }
    }
}

__device__ __forceinline__ float fmax4(float4 f) {
    return fmaxf(fmaxf(f.x, f.y), fmaxf(f.z, f.w));
}

__device__ __forceinline__ void emit4(float4 f, int base, float T,
                                      int* s_count, float* s_cval, int* s_cidx) {
    if (f.x >= T) { int p = atomicAdd(s_count, 1); if (p < CAP) { s_cval[p] = f.x; s_cidx[p] = base + 0; } }
    if (f.y >= T) { int p = atomicAdd(s_count, 1); if (p < CAP) { s_cval[p] = f.y; s_cidx[p] = base + 1; } }
    if (f.z >= T) { int p = atomicAdd(s_count, 1); if (p < CAP) { s_cval[p] = f.z; s_cidx[p] = base + 2; } }
    if (f.w >= T) { int p = atomicAdd(s_count, 1); if (p < CAP) { s_cval[p] = f.w; s_cidx[p] = base + 3; } }
}

__global__ __launch_bounds__(NTHREADS, 7)
void user_blend_kernel(const int* __restrict__ user_idx,
                       const float* __restrict__ emb,
                       const float* __restrict__ cooc,
                       float* __restrict__ out)
{
    __shared__ float s_wmax[NWARPS];
    __shared__ float s_cval[CAP];
    __shared__ int   s_cidx[CAP];
    __shared__ int   s_count;
    __shared__ float s_w[KSEL];
    __shared__ int   s_idx[KSEL];

    const int t = threadIdx.x;
    const int lane = t & 31;
    const int warp = t >> 5;
    const int u = user_idx[blockIdx.x];
    const float4* __restrict__ row4 =
        reinterpret_cast<const float4*>(cooc + (size_t)u * NUM_USERS);

    // ---------- Phase 0: threshold from the first 4096 elements ----------
    // Evict-first (.cs) loads: the row is a read-once stream; keep only the
    // per-thread max pm (1 reg) across the barrier. The rare pm>=T threads
    // re-read their 4 groups right after (still cache-resident in the short
    // window, and worst case a few MB of extra DRAM chip-wide).
    float pm;
    {
        float4 a = __ldcs(&row4[t]);
        float4 b = __ldcs(&row4[t + NTHREADS]);
        float4 c = __ldcs(&row4[t + 2 * NTHREADS]);
        float4 d = __ldcs(&row4[t + 3 * NTHREADS]);
        pm = fmaxf(fmaxf(fmax4(a), fmax4(b)), fmaxf(fmax4(c), fmax4(d)));
        float wm = pm;
        #pragma unroll
        for (int s = 16; s >= 1; s >>= 1)
            wm = fmaxf(wm, __shfl_xor_sync(0xffffffffu, wm, s));
        if (lane == 0) s_wmax[warp] = wm;
        if (t == 0) s_count = 0;
    }
    __syncthreads();

    // Every thread redundantly computes T = 6th-largest of the 8 warp maxes.
    // Safe lower bound: the 6 largest warp-maxes are >=6 distinct row elements,
    // so T <= true 6th-largest of the row. Filter with >= preserves exactness.
    float T;
    {
        float top[KP1];
        #pragma unroll
        for (int j = 0; j < KP1; j++) top[j] = -3.0e38f;
        #pragma unroll
        for (int k = 0; k < NWARPS; k++) {
            float v = s_wmax[k];   // broadcast read
            #pragma unroll
            for (int j = 0; j < KP1; j++) {
                float lo = fminf(top[j], v);
                top[j]   = fmaxf(top[j], v);
                v = lo;
            }
        }
        T = top[KP1 - 1];
    }

    // ---------- Prefix emit: only threads whose prefix max passed T ----------
    if (pm >= T) {
        float4 a = __ldcs(&row4[t]);
        float4 b = __ldcs(&row4[t + NTHREADS]);
        float4 c = __ldcs(&row4[t + 2 * NTHREADS]);
        float4 d = __ldcs(&row4[t + 3 * NTHREADS]);
        if (fmax4(a) >= T) emit4(a, t * 4,                  T, &s_count, s_cval, s_cidx);
        if (fmax4(b) >= T) emit4(b, (t + NTHREADS) * 4,     T, &s_count, s_cval, s_cidx);
        if (fmax4(c) >= T) emit4(c, (t + 2 * NTHREADS) * 4, T, &s_count, s_cval, s_cidx);
        if (fmax4(d) >= T) emit4(d, (t + 3 * NTHREADS) * 4, T, &s_count, s_cval, s_cidx);
    }

    // ---------- Phase 1a: groups 1024..4095, unclamped 4-deep .cs batches ----------
    #pragma unroll 1
    for (int b = 1; b < 4; b++) {
        int i0 = t + b * 4 * NTHREADS;
        float4 a = __ldcs(&row4[i0]);
        float4 c = __ldcs(&row4[i0 + NTHREADS]);
        float4 d = __ldcs(&row4[i0 + 2 * NTHREADS]);
        float4 e = __ldcs(&row4[i0 + 3 * NTHREADS]);
        float ma = fmax4(a);
        float mc = fmax4(c);
        float md = fmax4(d);
        float me = fmax4(e);
        float bm = fmaxf(fmaxf(ma, mc), fmaxf(md, me));
        if (bm >= T) {                 // rare
            if (ma >= T) emit4(a, i0 * 4,                  T, &s_count, s_cval, s_cidx);
            if (mc >= T) emit4(c, (i0 + NTHREADS) * 4,     T, &s_count, s_cval, s_cidx);
            if (md >= T) emit4(d, (i0 + 2 * NTHREADS) * 4, T, &s_count, s_cval, s_cidx);
            if (me >= T) emit4(e, (i0 + 3 * NTHREADS) * 4, T, &s_count, s_cval, s_cidx);
        }
    }

    // ---------- Phase 1b: tail groups 4096..4999 (the only clamped batch) ----------
    {
        int i0 = t + 4 * 4 * NTHREADS;          // 4096 + t
        int i1 = i0 + NTHREADS;
        int i2 = i0 + 2 * NTHREADS;
        int i3 = i0 + 3 * NTHREADS;
        float4 a = __ldcs(&row4[min(i0, ROW4 - 1)]);
        float4 c = __ldcs(&row4[min(i1, ROW4 - 1)]);
        float4 d = __ldcs(&row4[min(i2, ROW4 - 1)]);
        float4 e = __ldcs(&row4[min(i3, ROW4 - 1)]);
        float ma = (i0 < ROW4) ? fmax4(a) : -3.0e38f;
        float mc = (i1 < ROW4) ? fmax4(c) : -3.0e38f;
        float md = (i2 < ROW4) ? fmax4(d) : -3.0e38f;
        float me = (i3 < ROW4) ? fmax4(e) : -3.0e38f;
        float bm = fmaxf(fmaxf(ma, mc), fmaxf(md, me));
        if (bm >= T) {
            if (ma >= T) emit4(a, i0 * 4, T, &s_count, s_cval, s_cidx);
            if (mc >= T) emit4(c, i1 * 4, T, &s_count, s_cval, s_cidx);
            if (md >= T) emit4(d, i2 * 4, T, &s_count, s_cval, s_cidx);
            if (me >= T) emit4(e, i3 * 4, T, &s_count, s_cval, s_cidx);
        }
    }
    __syncthreads();

    // ---------- Final exact top-6, softmax, weights (serial tail: proven) ----------
    if (t == 0) {
        VI best[KP1];
        #pragma unroll
        for (int j = 0; j < KP1; j++) { best[j].v = -3.0e38f; best[j].i = 0x7fffffff; }

        int cnt = s_count;
        if (cnt <= CAP) {
            for (int k = 0; k < cnt; k++)
                exact_insert(best, s_cval[k], s_cidx[k]);
        } else {
            // Overflow fallback (adversarial ties only): serial exact scan.
            const float* row = cooc + (size_t)u * NUM_USERS;
            for (int k = 0; k < NUM_USERS; k++)
                exact_insert(best, row[k], k);
        }

        // Drop slot 0 (the max), softmax over slots 1..5.
        float m = best[1].v;
        float e[KSEL];
        float sum = 0.0f;
        #pragma unroll
        for (int j = 0; j < KSEL; j++) {
            e[j] = __expf(best[j + 1].v - m);
            sum += e[j];
        }
        float inv = 1.0f / sum;
        #pragma unroll
        for (int j = 0; j < KSEL; j++) {
            s_w[j]   = e[j] * inv;
            s_idx[j] = best[j + 1].i;
        }
    }
    __syncthreads();

    // ---------- Blend ----------
    if (t < EMBED_DIM) {
        float acc = 0.0f;
        #pragma unroll
        for (int j = 0; j < KSEL; j++)
            acc += s_w[j] * emb[(size_t)s_idx[j] * EMBED_DIM + t];
        float self = emb[(size_t)u * EMBED_DIM + t];
        out[(size_t)blockIdx.x * EMBED_DIM + t] = ALPHA_F * self + (1.0f - ALPHA_F) * acc;
    }
}

extern "C" void kernel_launch(void* const* d_in, const int* in_sizes, int n_in,
                              void* d_out, int out_size)
{
    // Identify inputs by element count:
    //   user_idx: 4096 (int32), emb: 20000*64 (f32), cooc: 20000*20000 (f32)
    const int*   user_idx = nullptr;
    const float* emb      = nullptr;
    const float* cooc     = nullptr;
    int batch = 0;
    for (int i = 0; i < n_in; i++) {
        long long sz = in_sizes[i];
        if (sz == (long long)NUM_USERS * NUM_USERS) {
            cooc = (const float*)d_in[i];
        } else if (sz == (long long)NUM_USERS * EMBED_DIM) {
            emb = (const float*)d_in[i];
        } else {
            user_idx = (const int*)d_in[i];
            batch = (int)sz;
        }
    }
    float* out = (float*)d_out;
    user_blend_kernel<<<batch, NTHREADS>>>(user_idx, emb, cooc, out);
}